// round 1
// baseline (speedup 1.0000x reference)
#include <cuda_runtime.h>

#define H 1024
#define SEQ 2048
#define VOC 50257

// ---------------- device scratch (static, allocation-guard safe) ----------------
__device__ __align__(16) float g_x0[2 * H];     // [emb_row, last_context]
__device__ __align__(16) float g_h0[H];
__device__ __align__(16) float g_h1[H];
__device__ __align__(16) float g_v[H];          // Wa^T @ h1
__device__ float g_c;                            // ba . h1
__device__ __align__(16) float g_scores[SEQ];
__device__ __align__(16) float g_attn[SEQ];
__device__ __align__(16) float g_cpart[16 * H];
__device__ __align__(16) float g_context[H];
__device__ __align__(16) float g_logits[VOC];
__device__ float g_logZ;

__device__ __forceinline__ float warp_sum(float v) {
    #pragma unroll
    for (int o = 16; o; o >>= 1) v += __shfl_xor_sync(0xffffffffu, v, o);
    return v;
}
__device__ __forceinline__ float warp_max(float v) {
    #pragma unroll
    for (int o = 16; o; o >>= 1) v = fmaxf(v, __shfl_xor_sync(0xffffffffu, v, o));
    return v;
}

// ---------------- K0: x0 = concat(emb[word], last_context) ----------------
__global__ void k_build_x0(const int* __restrict__ word,
                           const float* __restrict__ emb,
                           const float* __restrict__ last_context) {
    int k = blockIdx.x * blockDim.x + threadIdx.x;
    if (k < H) {
        g_x0[k] = emb[(size_t)word[0] * H + k];
    } else if (k < 2 * H) {
        g_x0[k] = last_context[k - H];
    }
}

// ---------------- GRU cell: warp per output dim j (1024 warps) ----------------
// gi = W_ih @ x + b_ih ; gh = W_hh @ h + b_hh
// r = sig(gi_r+gh_r), z = sig(gi_z+gh_z), n = tanh(gi_n + r*gh_n)
// h' = (1-z)*n + z*h
template <int XDIM, bool FIRST>
__global__ void k_gru(const float* __restrict__ W_ih, const float* __restrict__ W_hh,
                      const float* __restrict__ b_ih, const float* __restrict__ b_hh,
                      const float* __restrict__ h_prev, float* __restrict__ out_hidden) {
    int warp = (blockIdx.x * blockDim.x + threadIdx.x) >> 5;
    int lane = threadIdx.x & 31;
    if (warp >= H) return;

    const float* x = FIRST ? g_x0 : g_h0;
    const float4* xv = (const float4*)x;
    const float4* wr = (const float4*)(W_ih + (size_t)warp * XDIM);
    const float4* wz = (const float4*)(W_ih + (size_t)(warp + H) * XDIM);
    const float4* wn = (const float4*)(W_ih + (size_t)(warp + 2 * H) * XDIM);

    float ar = 0.f, az = 0.f, an = 0.f;
    #pragma unroll
    for (int t = 0; t < XDIM / 128; t++) {
        int i = lane + t * 32;
        float4 xx = xv[i];
        float4 a = wr[i];
        float4 b = wz[i];
        float4 c = wn[i];
        ar += xx.x * a.x + xx.y * a.y + xx.z * a.z + xx.w * a.w;
        az += xx.x * b.x + xx.y * b.y + xx.z * b.z + xx.w * b.w;
        an += xx.x * c.x + xx.y * c.y + xx.z * c.z + xx.w * c.w;
    }

    const float4* hv = (const float4*)h_prev;
    const float4* ur = (const float4*)(W_hh + (size_t)warp * H);
    const float4* uz = (const float4*)(W_hh + (size_t)(warp + H) * H);
    const float4* un = (const float4*)(W_hh + (size_t)(warp + 2 * H) * H);

    float br = 0.f, bz = 0.f, bn = 0.f;
    #pragma unroll
    for (int t = 0; t < H / 128; t++) {
        int i = lane + t * 32;
        float4 hh = hv[i];
        float4 a = ur[i];
        float4 b = uz[i];
        float4 c = un[i];
        br += hh.x * a.x + hh.y * a.y + hh.z * a.z + hh.w * a.w;
        bz += hh.x * b.x + hh.y * b.y + hh.z * b.z + hh.w * b.w;
        bn += hh.x * c.x + hh.y * c.y + hh.z * c.z + hh.w * c.w;
    }

    ar = warp_sum(ar); az = warp_sum(az); an = warp_sum(an);
    br = warp_sum(br); bz = warp_sum(bz); bn = warp_sum(bn);

    if (lane == 0) {
        float ir = ar + b_ih[warp];
        float iz = az + b_ih[warp + H];
        float in_ = an + b_ih[warp + 2 * H];
        float hr = br + b_hh[warp];
        float hz = bz + b_hh[warp + H];
        float hn = bn + b_hh[warp + 2 * H];
        float r = 1.f / (1.f + expf(-(ir + hr)));
        float z = 1.f / (1.f + expf(-(iz + hz)));
        float n = tanhf(in_ + r * hn);
        float hp = h_prev[warp];
        float ho = (1.f - z) * n + z * hp;
        if (FIRST) g_h0[warp] = ho; else g_h1[warp] = ho;
        out_hidden[warp] = ho;
    }
}

// ---------------- K3: v = Wa^T @ h1 (column GEMV) ; c = ba.h1 ----------------
__global__ void k_v(const float* __restrict__ Wa, const float* __restrict__ ba) {
    __shared__ float sh[H];
    int tid = threadIdx.x;  // 128 threads

    if (blockIdx.x == 8) {  // compute c = dot(ba, h1)
        float a = 0.f;
        for (int i = tid; i < H; i += 128) a += ba[i] * g_h1[i];
        a = warp_sum(a);
        __shared__ float red[4];
        if ((tid & 31) == 0) red[tid >> 5] = a;
        __syncthreads();
        if (tid == 0) g_c = red[0] + red[1] + red[2] + red[3];
        return;
    }

    for (int i = tid; i < H; i += 128) sh[i] = g_h1[i];
    __syncthreads();

    int j = blockIdx.x * 128 + tid;
    float a0 = 0.f, a1 = 0.f, a2 = 0.f, a3 = 0.f;
    #pragma unroll 4
    for (int i = 0; i < H; i += 4) {
        a0 += Wa[(size_t)(i + 0) * H + j] * sh[i + 0];
        a1 += Wa[(size_t)(i + 1) * H + j] * sh[i + 1];
        a2 += Wa[(size_t)(i + 2) * H + j] * sh[i + 2];
        a3 += Wa[(size_t)(i + 3) * H + j] * sh[i + 3];
    }
    g_v[j] = (a0 + a1) + (a2 + a3);
}

// ---------------- K4: scores[s] = enc[s,:].v + c  (warp per s) ----------------
__global__ void k_scores(const float* __restrict__ enc) {
    int warp = (blockIdx.x * blockDim.x + threadIdx.x) >> 5;
    int lane = threadIdx.x & 31;
    if (warp >= SEQ) return;
    const float4* e = (const float4*)(enc + (size_t)warp * H);
    const float4* vv = (const float4*)g_v;
    float acc = 0.f;
    #pragma unroll
    for (int t = 0; t < H / 128; t++) {
        int i = lane + t * 32;
        float4 a = e[i];
        float4 b = vv[i];
        acc += a.x * b.x + a.y * b.y + a.z * b.z + a.w * b.w;
    }
    acc = warp_sum(acc);
    if (lane == 0) g_scores[warp] = acc + g_c;
}

// ---------------- K5: softmax over 2048 scores (single block) ----------------
__global__ void k_softmax(float* __restrict__ out_attn) {
    __shared__ float red[32];
    __shared__ float bc;
    int tid = threadIdx.x;  // 1024 threads = 32 warps

    float m = -1e30f;
    for (int s = tid; s < SEQ; s += 1024) m = fmaxf(m, g_scores[s]);
    m = warp_max(m);
    if ((tid & 31) == 0) red[tid >> 5] = m;
    __syncthreads();
    if (tid < 32) {
        float v = warp_max(red[tid]);
        if (tid == 0) bc = v;
    }
    __syncthreads();
    float M = bc;

    float sum = 0.f;
    for (int s = tid; s < SEQ; s += 1024) {
        float e = expf(g_scores[s] - M);
        g_attn[s] = e;
        sum += e;
    }
    sum = warp_sum(sum);
    if ((tid & 31) == 0) red[tid >> 5] = sum;
    __syncthreads();
    if (tid < 32) {
        float v = warp_sum(red[tid]);
        if (tid == 0) bc = 1.f / v;
    }
    __syncthreads();
    float inv = bc;
    for (int s = tid; s < SEQ; s += 1024) {
        float w = g_attn[s] * inv;
        g_attn[s] = w;
        out_attn[s] = w;
    }
}

// ---------------- K6: context partials over s-chunks ----------------
__global__ void k_ctx_part(const float* __restrict__ enc) {
    __shared__ float wsh[128];
    int tid = threadIdx.x;  // 128
    int s0 = blockIdx.y * 128;
    wsh[tid] = g_attn[s0 + tid];
    __syncthreads();
    int j = blockIdx.x * 128 + tid;
    float a0 = 0.f, a1 = 0.f, a2 = 0.f, a3 = 0.f;
    #pragma unroll 4
    for (int ss = 0; ss < 128; ss += 4) {
        a0 += wsh[ss + 0] * enc[(size_t)(s0 + ss + 0) * H + j];
        a1 += wsh[ss + 1] * enc[(size_t)(s0 + ss + 1) * H + j];
        a2 += wsh[ss + 2] * enc[(size_t)(s0 + ss + 2) * H + j];
        a3 += wsh[ss + 3] * enc[(size_t)(s0 + ss + 3) * H + j];
    }
    g_cpart[blockIdx.y * H + j] = (a0 + a1) + (a2 + a3);
}

// ---------------- K7: reduce 16 partials -> context ----------------
__global__ void k_ctx_reduce(float* __restrict__ out_context) {
    int j = blockIdx.x * blockDim.x + threadIdx.x;
    if (j >= H) return;
    float a = 0.f;
    #pragma unroll
    for (int y = 0; y < 16; y++) a += g_cpart[y * H + j];
    g_context[j] = a;
    out_context[j] = a;
}

// ---------------- K8: logits = W_out @ [h1, context] + b_out (warp per row) ----------------
__global__ void k_logits(const float* __restrict__ W_out, const float* __restrict__ b_out) {
    __shared__ __align__(16) float u[2 * H];
    for (int k = threadIdx.x; k < 2 * H; k += 256) {
        u[k] = (k < H) ? g_h1[k] : g_context[k - H];
    }
    __syncthreads();

    int r = blockIdx.x * 8 + (threadIdx.x >> 5);
    if (r >= VOC) return;
    int lane = threadIdx.x & 31;
    const float4* w = (const float4*)(W_out + (size_t)r * (2 * H));
    const float4* uv = (const float4*)u;
    float acc0 = 0.f, acc1 = 0.f;
    #pragma unroll
    for (int t = 0; t < 8; t++) {
        int i0 = lane + (2 * t) * 32;
        int i1 = lane + (2 * t + 1) * 32;
        float4 a = w[i0];
        float4 b = uv[i0];
        acc0 += a.x * b.x + a.y * b.y + a.z * b.z + a.w * b.w;
        float4 c = w[i1];
        float4 d = uv[i1];
        acc1 += c.x * d.x + c.y * d.y + c.z * d.z + c.w * d.w;
    }
    float acc = warp_sum(acc0 + acc1);
    if (lane == 0) g_logits[r] = acc + b_out[r];
}

// ---------------- K9: logZ = max + log(sum(exp(logits - max))) ----------------
__global__ void k_lse() {
    __shared__ float red[32];
    __shared__ float bc;
    int tid = threadIdx.x;  // 1024

    float m = -1e30f;
    for (int r = tid; r < VOC; r += 1024) m = fmaxf(m, g_logits[r]);
    m = warp_max(m);
    if ((tid & 31) == 0) red[tid >> 5] = m;
    __syncthreads();
    if (tid < 32) {
        float v = warp_max(red[tid]);
        if (tid == 0) bc = v;
    }
    __syncthreads();
    float M = bc;

    float sum = 0.f;
    for (int r = tid; r < VOC; r += 1024) sum += expf(g_logits[r] - M);
    sum = warp_sum(sum);
    if ((tid & 31) == 0) red[tid >> 5] = sum;
    __syncthreads();
    if (tid < 32) {
        float v = warp_sum(red[tid]);
        if (tid == 0) g_logZ = M + logf(v);
    }
}

// ---------------- K10: output = logits - logZ ----------------
__global__ void k_out(float* __restrict__ out) {
    float lz = g_logZ;
    for (int r = blockIdx.x * blockDim.x + threadIdx.x; r < VOC; r += gridDim.x * blockDim.x) {
        out[r] = g_logits[r] - lz;
    }
}

// ---------------- launch ----------------
extern "C" void kernel_launch(void* const* d_in, const int* in_sizes, int n_in,
                              void* d_out, int out_size) {
    const int*   word         = (const int*)  d_in[0];
    const float* last_context = (const float*)d_in[1];
    const float* last_hidden  = (const float*)d_in[2];
    const float* enc          = (const float*)d_in[3];
    const float* emb          = (const float*)d_in[4];
    const float* W_ih0        = (const float*)d_in[5];
    const float* W_hh0        = (const float*)d_in[6];
    const float* b_ih0        = (const float*)d_in[7];
    const float* b_hh0        = (const float*)d_in[8];
    const float* W_ih1        = (const float*)d_in[9];
    const float* W_hh1        = (const float*)d_in[10];
    const float* b_ih1        = (const float*)d_in[11];
    const float* b_hh1        = (const float*)d_in[12];
    const float* Wa           = (const float*)d_in[13];
    const float* ba           = (const float*)d_in[14];
    const float* W_out        = (const float*)d_in[15];
    const float* b_out        = (const float*)d_in[16];
    float* out = (float*)d_out;

    // d_out layout: [output VOC | context H | hidden 2H | attn SEQ]
    float* out_context = out + VOC;
    float* out_h0      = out + VOC + H;
    float* out_h1      = out + VOC + 2 * H;
    float* out_attn    = out + VOC + 3 * H;

    k_build_x0<<<8, 256>>>(word, emb, last_context);
    k_gru<2 * H, true ><<<128, 256>>>(W_ih0, W_hh0, b_ih0, b_hh0, last_hidden,     out_h0);
    k_gru<    H, false><<<128, 256>>>(W_ih1, W_hh1, b_ih1, b_hh1, last_hidden + H, out_h1);
    k_v<<<9, 128>>>(Wa, ba);
    k_scores<<<SEQ / 8, 256>>>(enc);
    k_softmax<<<1, 1024>>>(out_attn);
    {
        dim3 g(8, 16);
        k_ctx_part<<<g, 128>>>(enc);
    }
    k_ctx_reduce<<<4, 256>>>(out_context);
    k_logits<<<(VOC + 7) / 8, 256>>>(W_out, b_out);
    k_lse<<<1, 1024>>>();
    k_out<<<200, 256>>>(out);
}

// round 2
// speedup vs baseline: 1.4172x; 1.4172x over previous
#include <cuda_runtime.h>

#define H 1024
#define SEQ 2048
#define VOC 50257

// ---------------- device scratch (static, allocation-guard safe) ----------------
__device__ __align__(16) float g_x0[2 * H];     // [emb_row, last_context]
__device__ __align__(16) float g_h0[H];
__device__ __align__(16) float g_h1[H];
__device__ __align__(16) float g_v[H];          // Wa^T @ h1
__device__ float g_c;                            // ba . h1
__device__ __align__(16) float g_scores[SEQ];
__device__ __align__(16) float g_attn[SEQ];
__device__ __align__(16) float g_vpart[64 * H];
__device__ __align__(16) float g_cpart[64 * H];
__device__ __align__(16) float g_context[H];
__device__ __align__(16) float g_logits[VOC];
__device__ float g_logZ;

__device__ __forceinline__ float warp_sum(float v) {
    #pragma unroll
    for (int o = 16; o; o >>= 1) v += __shfl_xor_sync(0xffffffffu, v, o);
    return v;
}
__device__ __forceinline__ float warp_max(float v) {
    #pragma unroll
    for (int o = 16; o; o >>= 1) v = fmaxf(v, __shfl_xor_sync(0xffffffffu, v, o));
    return v;
}

// ---------------- K0: x0 = concat(emb[word], last_context) ----------------
__global__ void k_build_x0(const int* __restrict__ word,
                           const float* __restrict__ emb,
                           const float* __restrict__ last_context) {
    int k = blockIdx.x * blockDim.x + threadIdx.x;
    if (k < H) {
        g_x0[k] = emb[(size_t)word[0] * H + k];
    } else if (k < 2 * H) {
        g_x0[k] = last_context[k - H];
    }
}

// ---------------- GRU cell: warp per output dim j (1024 warps) ----------------
template <int XDIM, bool FIRST>
__global__ void k_gru(const float* __restrict__ W_ih, const float* __restrict__ W_hh,
                      const float* __restrict__ b_ih, const float* __restrict__ b_hh,
                      const float* __restrict__ h_prev, float* __restrict__ out_hidden) {
    int warp = (blockIdx.x * blockDim.x + threadIdx.x) >> 5;
    int lane = threadIdx.x & 31;
    if (warp >= H) return;

    const float* x = FIRST ? g_x0 : g_h0;
    const float4* xv = (const float4*)x;
    const float4* wr = (const float4*)(W_ih + (size_t)warp * XDIM);
    const float4* wz = (const float4*)(W_ih + (size_t)(warp + H) * XDIM);
    const float4* wn = (const float4*)(W_ih + (size_t)(warp + 2 * H) * XDIM);

    float ar = 0.f, az = 0.f, an = 0.f;
    #pragma unroll
    for (int t = 0; t < XDIM / 128; t++) {
        int i = lane + t * 32;
        float4 xx = xv[i];
        float4 a = wr[i];
        float4 b = wz[i];
        float4 c = wn[i];
        ar += xx.x * a.x + xx.y * a.y + xx.z * a.z + xx.w * a.w;
        az += xx.x * b.x + xx.y * b.y + xx.z * b.z + xx.w * b.w;
        an += xx.x * c.x + xx.y * c.y + xx.z * c.z + xx.w * c.w;
    }

    const float4* hv = (const float4*)h_prev;
    const float4* ur = (const float4*)(W_hh + (size_t)warp * H);
    const float4* uz = (const float4*)(W_hh + (size_t)(warp + H) * H);
    const float4* un = (const float4*)(W_hh + (size_t)(warp + 2 * H) * H);

    float br = 0.f, bz = 0.f, bn = 0.f;
    #pragma unroll
    for (int t = 0; t < H / 128; t++) {
        int i = lane + t * 32;
        float4 hh = hv[i];
        float4 a = ur[i];
        float4 b = uz[i];
        float4 c = un[i];
        br += hh.x * a.x + hh.y * a.y + hh.z * a.z + hh.w * a.w;
        bz += hh.x * b.x + hh.y * b.y + hh.z * b.z + hh.w * b.w;
        bn += hh.x * c.x + hh.y * c.y + hh.z * c.z + hh.w * c.w;
    }

    ar = warp_sum(ar); az = warp_sum(az); an = warp_sum(an);
    br = warp_sum(br); bz = warp_sum(bz); bn = warp_sum(bn);

    if (lane == 0) {
        float ir = ar + b_ih[warp];
        float iz = az + b_ih[warp + H];
        float in_ = an + b_ih[warp + 2 * H];
        float hr = br + b_hh[warp];
        float hz = bz + b_hh[warp + H];
        float hn = bn + b_hh[warp + 2 * H];
        float r = 1.f / (1.f + expf(-(ir + hr)));
        float z = 1.f / (1.f + expf(-(iz + hz)));
        float n = tanhf(in_ + r * hn);
        float hp = h_prev[warp];
        float ho = (1.f - z) * n + z * hp;
        if (FIRST) g_h0[warp] = ho; else g_h1[warp] = ho;
        out_hidden[warp] = ho;
    }
}

// ---------------- K3a: v partials — weighted row-sum of Wa, coalesced ----------------
// chunk c covers rows [c*16, c*16+16); vpart[c][j] = sum_ss h1[row] * Wa[row][j]
__global__ void k_v_part(const float* __restrict__ Wa) {
    __shared__ float hsh[16];
    int tid = threadIdx.x;  // 128
    int r0 = blockIdx.y * 16;
    if (tid < 16) hsh[tid] = g_h1[r0 + tid];
    __syncthreads();
    int j = blockIdx.x * 128 + tid;
    float a0 = 0.f, a1 = 0.f, a2 = 0.f, a3 = 0.f;
    #pragma unroll
    for (int ss = 0; ss < 16; ss += 4) {
        a0 += hsh[ss + 0] * Wa[(size_t)(r0 + ss + 0) * H + j];
        a1 += hsh[ss + 1] * Wa[(size_t)(r0 + ss + 1) * H + j];
        a2 += hsh[ss + 2] * Wa[(size_t)(r0 + ss + 2) * H + j];
        a3 += hsh[ss + 3] * Wa[(size_t)(r0 + ss + 3) * H + j];
    }
    g_vpart[blockIdx.y * H + j] = (a0 + a1) + (a2 + a3);
}

// ---------------- K3b: v = reduce(vpart) ; c = ba.h1 ----------------
__global__ void k_v_reduce(const float* __restrict__ ba) {
    int tid = threadIdx.x;  // 256
    if (blockIdx.x == 4) {  // c = dot(ba, h1)
        float a = 0.f;
        for (int i = tid; i < H; i += 256) a += ba[i] * g_h1[i];
        a = warp_sum(a);
        __shared__ float red[8];
        if ((tid & 31) == 0) red[tid >> 5] = a;
        __syncthreads();
        if (tid == 0) {
            float s = 0.f;
            #pragma unroll
            for (int i = 0; i < 8; i++) s += red[i];
            g_c = s;
        }
        return;
    }
    int j = blockIdx.x * 256 + tid;
    float a = 0.f;
    #pragma unroll
    for (int y = 0; y < 64; y++) a += g_vpart[y * H + j];
    g_v[j] = a;
}

// ---------------- K4: scores[s] = enc[s,:].v + c  (warp per s) ----------------
__global__ void k_scores(const float* __restrict__ enc) {
    int warp = (blockIdx.x * blockDim.x + threadIdx.x) >> 5;
    int lane = threadIdx.x & 31;
    if (warp >= SEQ) return;
    const float4* e = (const float4*)(enc + (size_t)warp * H);
    const float4* vv = (const float4*)g_v;
    float acc = 0.f;
    #pragma unroll
    for (int t = 0; t < H / 128; t++) {
        int i = lane + t * 32;
        float4 a = e[i];
        float4 b = vv[i];
        acc += a.x * b.x + a.y * b.y + a.z * b.z + a.w * b.w;
    }
    acc = warp_sum(acc);
    if (lane == 0) g_scores[warp] = acc + g_c;
}

// ---------------- K5: softmax over 2048 scores (single block) ----------------
__global__ void k_softmax(float* __restrict__ out_attn) {
    __shared__ float red[32];
    __shared__ float bc;
    int tid = threadIdx.x;  // 1024 threads = 32 warps

    float m = -1e30f;
    for (int s = tid; s < SEQ; s += 1024) m = fmaxf(m, g_scores[s]);
    m = warp_max(m);
    if ((tid & 31) == 0) red[tid >> 5] = m;
    __syncthreads();
    if (tid < 32) {
        float v = warp_max(red[tid]);
        if (tid == 0) bc = v;
    }
    __syncthreads();
    float M = bc;

    float sum = 0.f;
    for (int s = tid; s < SEQ; s += 1024) {
        float e = expf(g_scores[s] - M);
        g_attn[s] = e;
        sum += e;
    }
    sum = warp_sum(sum);
    if ((tid & 31) == 0) red[tid >> 5] = sum;
    __syncthreads();
    if (tid < 32) {
        float v = warp_sum(red[tid]);
        if (tid == 0) bc = 1.f / v;
    }
    __syncthreads();
    float inv = bc;
    for (int s = tid; s < SEQ; s += 1024) {
        float w = g_attn[s] * inv;
        g_attn[s] = w;
        out_attn[s] = w;
    }
}

// ---------------- K6: context partials — 64 chunks of 32 rows, coalesced ----------------
__global__ void k_ctx_part(const float* __restrict__ enc) {
    __shared__ float wsh[32];
    int tid = threadIdx.x;  // 128
    int s0 = blockIdx.y * 32;
    if (tid < 32) wsh[tid] = g_attn[s0 + tid];
    __syncthreads();
    int j = blockIdx.x * 128 + tid;
    float a0 = 0.f, a1 = 0.f, a2 = 0.f, a3 = 0.f;
    #pragma unroll
    for (int ss = 0; ss < 32; ss += 4) {
        a0 += wsh[ss + 0] * enc[(size_t)(s0 + ss + 0) * H + j];
        a1 += wsh[ss + 1] * enc[(size_t)(s0 + ss + 1) * H + j];
        a2 += wsh[ss + 2] * enc[(size_t)(s0 + ss + 2) * H + j];
        a3 += wsh[ss + 3] * enc[(size_t)(s0 + ss + 3) * H + j];
    }
    g_cpart[blockIdx.y * H + j] = (a0 + a1) + (a2 + a3);
}

// ---------------- K7: reduce 64 partials -> context ----------------
__global__ void k_ctx_reduce(float* __restrict__ out_context) {
    int j = blockIdx.x * blockDim.x + threadIdx.x;
    if (j >= H) return;
    float a = 0.f;
    #pragma unroll
    for (int y = 0; y < 64; y++) a += g_cpart[y * H + j];
    g_context[j] = a;
    out_context[j] = a;
}

// ---------------- K8: logits = W_out @ [h1, context] + b_out (warp per row) ----------------
__global__ void k_logits(const float* __restrict__ W_out, const float* __restrict__ b_out) {
    __shared__ __align__(16) float u[2 * H];
    for (int k = threadIdx.x; k < 2 * H; k += 256) {
        u[k] = (k < H) ? g_h1[k] : g_context[k - H];
    }
    __syncthreads();

    int r = blockIdx.x * 8 + (threadIdx.x >> 5);
    if (r >= VOC) return;
    int lane = threadIdx.x & 31;
    const float4* w = (const float4*)(W_out + (size_t)r * (2 * H));
    const float4* uv = (const float4*)u;
    float acc0 = 0.f, acc1 = 0.f;
    #pragma unroll
    for (int t = 0; t < 8; t++) {
        int i0 = lane + (2 * t) * 32;
        int i1 = lane + (2 * t + 1) * 32;
        float4 a = w[i0];
        float4 b = uv[i0];
        acc0 += a.x * b.x + a.y * b.y + a.z * b.z + a.w * b.w;
        float4 c = w[i1];
        float4 d = uv[i1];
        acc1 += c.x * d.x + c.y * d.y + c.z * d.z + c.w * d.w;
    }
    float acc = warp_sum(acc0 + acc1);
    if (lane == 0) g_logits[r] = acc + b_out[r];
}

// ---------------- K9: logZ = max + log(sum(exp(logits - max))) ----------------
__global__ void k_lse() {
    __shared__ float red[32];
    __shared__ float bc;
    int tid = threadIdx.x;  // 1024

    float m = -1e30f;
    for (int r = tid; r < VOC; r += 1024) m = fmaxf(m, g_logits[r]);
    m = warp_max(m);
    if ((tid & 31) == 0) red[tid >> 5] = m;
    __syncthreads();
    if (tid < 32) {
        float v = warp_max(red[tid]);
        if (tid == 0) bc = v;
    }
    __syncthreads();
    float M = bc;

    float sum = 0.f;
    for (int r = tid; r < VOC; r += 1024) sum += expf(g_logits[r] - M);
    sum = warp_sum(sum);
    if ((tid & 31) == 0) red[tid >> 5] = sum;
    __syncthreads();
    if (tid < 32) {
        float v = warp_sum(red[tid]);
        if (tid == 0) g_logZ = M + logf(v);
    }
}

// ---------------- K10: output = logits - logZ ----------------
__global__ void k_out(float* __restrict__ out) {
    float lz = g_logZ;
    for (int r = blockIdx.x * blockDim.x + threadIdx.x; r < VOC; r += gridDim.x * blockDim.x) {
        out[r] = g_logits[r] - lz;
    }
}

// ---------------- launch ----------------
extern "C" void kernel_launch(void* const* d_in, const int* in_sizes, int n_in,
                              void* d_out, int out_size) {
    const int*   word         = (const int*)  d_in[0];
    const float* last_context = (const float*)d_in[1];
    const float* last_hidden  = (const float*)d_in[2];
    const float* enc          = (const float*)d_in[3];
    const float* emb          = (const float*)d_in[4];
    const float* W_ih0        = (const float*)d_in[5];
    const float* W_hh0        = (const float*)d_in[6];
    const float* b_ih0        = (const float*)d_in[7];
    const float* b_hh0        = (const float*)d_in[8];
    const float* W_ih1        = (const float*)d_in[9];
    const float* W_hh1        = (const float*)d_in[10];
    const float* b_ih1        = (const float*)d_in[11];
    const float* b_hh1        = (const float*)d_in[12];
    const float* Wa           = (const float*)d_in[13];
    const float* ba           = (const float*)d_in[14];
    const float* W_out        = (const float*)d_in[15];
    const float* b_out        = (const float*)d_in[16];
    float* out = (float*)d_out;

    // d_out layout: [output VOC | context H | hidden 2H | attn S]
    float* out_context = out + VOC;
    float* out_h0      = out + VOC + H;
    float* out_h1      = out + VOC + 2 * H;
    float* out_attn    = out + VOC + 3 * H;

    k_build_x0<<<8, 256>>>(word, emb, last_context);
    k_gru<2 * H, true ><<<128, 256>>>(W_ih0, W_hh0, b_ih0, b_hh0, last_hidden,     out_h0);
    k_gru<    H, false><<<128, 256>>>(W_ih1, W_hh1, b_ih1, b_hh1, last_hidden + H, out_h1);
    {
        dim3 g(8, 64);
        k_v_part<<<g, 128>>>(Wa);
    }
    k_v_reduce<<<5, 256>>>(ba);
    k_scores<<<SEQ / 8, 256>>>(enc);
    k_softmax<<<1, 1024>>>(out_attn);
    {
        dim3 g(8, 64);
        k_ctx_part<<<g, 128>>>(enc);
    }
    k_ctx_reduce<<<4, 256>>>(out_context);
    k_logits<<<(VOC + 7) / 8, 256>>>(W_out, b_out);
    k_lse<<<1, 1024>>>();
    k_out<<<200, 256>>>(out);
}

// round 3
// speedup vs baseline: 1.4606x; 1.0306x over previous
#include <cuda_runtime.h>

#define H 1024
#define SEQ 2048
#define VOC 50257
#define LSE_BLOCKS 64

// ---------------- device scratch (static, allocation-guard safe) ----------------
__device__ __align__(16) float g_h0[H];
__device__ __align__(16) float g_h1[H];
__device__ __align__(16) float g_v[H];          // Wa^T @ h1
__device__ float g_c;                            // ba . h1
__device__ __align__(16) float g_scores[SEQ];
__device__ __align__(16) float g_attn[SEQ];
__device__ __align__(16) float g_vpart[64 * H];
__device__ __align__(16) float g_cpart[64 * H];
__device__ __align__(16) float g_context[H];
__device__ __align__(16) float g_logits[VOC];
__device__ float g_lse_m[LSE_BLOCKS];
__device__ float g_lse_s[LSE_BLOCKS];
__device__ float g_logZ;

__device__ __forceinline__ float warp_sum(float v) {
    #pragma unroll
    for (int o = 16; o; o >>= 1) v += __shfl_xor_sync(0xffffffffu, v, o);
    return v;
}
__device__ __forceinline__ float warp_max(float v) {
    #pragma unroll
    for (int o = 16; o; o >>= 1) v = fmaxf(v, __shfl_xor_sync(0xffffffffu, v, o));
    return v;
}

__global__ void k_warm() {}

// ---------------- GRU layer 0 (x0 = [emb[word], last_context] fused) ----------------
__global__ void k_gru0(const int* __restrict__ word,
                       const float* __restrict__ emb,
                       const float* __restrict__ last_context,
                       const float* __restrict__ W_ih, const float* __restrict__ W_hh,
                       const float* __restrict__ b_ih, const float* __restrict__ b_hh,
                       const float* __restrict__ h_prev, float* __restrict__ out_hidden) {
    const int XDIM = 2 * H;
    int warp = (blockIdx.x * blockDim.x + threadIdx.x) >> 5;
    int lane = threadIdx.x & 31;
    if (warp >= H) return;

    int w0 = word[0];
    const float4* emb4 = (const float4*)(emb + (size_t)w0 * H);
    const float4* ctx4 = (const float4*)last_context;
    const float4* wr = (const float4*)(W_ih + (size_t)warp * XDIM);
    const float4* wz = (const float4*)(W_ih + (size_t)(warp + H) * XDIM);
    const float4* wn = (const float4*)(W_ih + (size_t)(warp + 2 * H) * XDIM);

    float ar = 0.f, az = 0.f, an = 0.f;
    #pragma unroll
    for (int t = 0; t < 8; t++) {
        int i = lane + t * 32;
        float4 xx = emb4[i];
        float4 a = wr[i];
        float4 b = wz[i];
        float4 c = wn[i];
        ar += xx.x * a.x + xx.y * a.y + xx.z * a.z + xx.w * a.w;
        az += xx.x * b.x + xx.y * b.y + xx.z * b.z + xx.w * b.w;
        an += xx.x * c.x + xx.y * c.y + xx.z * c.z + xx.w * c.w;
    }
    #pragma unroll
    for (int t = 8; t < 16; t++) {
        int i = lane + t * 32;
        float4 xx = ctx4[i - 256];
        float4 a = wr[i];
        float4 b = wz[i];
        float4 c = wn[i];
        ar += xx.x * a.x + xx.y * a.y + xx.z * a.z + xx.w * a.w;
        az += xx.x * b.x + xx.y * b.y + xx.z * b.z + xx.w * b.w;
        an += xx.x * c.x + xx.y * c.y + xx.z * c.z + xx.w * c.w;
    }

    const float4* hv = (const float4*)h_prev;
    const float4* ur = (const float4*)(W_hh + (size_t)warp * H);
    const float4* uz = (const float4*)(W_hh + (size_t)(warp + H) * H);
    const float4* un = (const float4*)(W_hh + (size_t)(warp + 2 * H) * H);

    float br = 0.f, bz = 0.f, bn = 0.f;
    #pragma unroll
    for (int t = 0; t < 8; t++) {
        int i = lane + t * 32;
        float4 hh = hv[i];
        float4 a = ur[i];
        float4 b = uz[i];
        float4 c = un[i];
        br += hh.x * a.x + hh.y * a.y + hh.z * a.z + hh.w * a.w;
        bz += hh.x * b.x + hh.y * b.y + hh.z * b.z + hh.w * b.w;
        bn += hh.x * c.x + hh.y * c.y + hh.z * c.z + hh.w * c.w;
    }

    ar = warp_sum(ar); az = warp_sum(az); an = warp_sum(an);
    br = warp_sum(br); bz = warp_sum(bz); bn = warp_sum(bn);

    if (lane == 0) {
        float ir = ar + b_ih[warp];
        float iz = az + b_ih[warp + H];
        float in_ = an + b_ih[warp + 2 * H];
        float hr = br + b_hh[warp];
        float hz = bz + b_hh[warp + H];
        float hn = bn + b_hh[warp + 2 * H];
        float r = 1.f / (1.f + expf(-(ir + hr)));
        float z = 1.f / (1.f + expf(-(iz + hz)));
        float n = tanhf(in_ + r * hn);
        float hp = h_prev[warp];
        float ho = (1.f - z) * n + z * hp;
        g_h0[warp] = ho;
        out_hidden[warp] = ho;
    }
}

// ---------------- GRU layer 1 (x = g_h0) ----------------
__global__ void k_gru1(const float* __restrict__ W_ih, const float* __restrict__ W_hh,
                       const float* __restrict__ b_ih, const float* __restrict__ b_hh,
                       const float* __restrict__ h_prev, float* __restrict__ out_hidden) {
    int warp = (blockIdx.x * blockDim.x + threadIdx.x) >> 5;
    int lane = threadIdx.x & 31;
    if (warp >= H) return;

    const float4* xv = (const float4*)g_h0;
    const float4* wr = (const float4*)(W_ih + (size_t)warp * H);
    const float4* wz = (const float4*)(W_ih + (size_t)(warp + H) * H);
    const float4* wn = (const float4*)(W_ih + (size_t)(warp + 2 * H) * H);

    float ar = 0.f, az = 0.f, an = 0.f;
    #pragma unroll
    for (int t = 0; t < 8; t++) {
        int i = lane + t * 32;
        float4 xx = xv[i];
        float4 a = wr[i];
        float4 b = wz[i];
        float4 c = wn[i];
        ar += xx.x * a.x + xx.y * a.y + xx.z * a.z + xx.w * a.w;
        az += xx.x * b.x + xx.y * b.y + xx.z * b.z + xx.w * b.w;
        an += xx.x * c.x + xx.y * c.y + xx.z * c.z + xx.w * c.w;
    }

    const float4* hv = (const float4*)h_prev;
    const float4* ur = (const float4*)(W_hh + (size_t)warp * H);
    const float4* uz = (const float4*)(W_hh + (size_t)(warp + H) * H);
    const float4* un = (const float4*)(W_hh + (size_t)(warp + 2 * H) * H);

    float br = 0.f, bz = 0.f, bn = 0.f;
    #pragma unroll
    for (int t = 0; t < 8; t++) {
        int i = lane + t * 32;
        float4 hh = hv[i];
        float4 a = ur[i];
        float4 b = uz[i];
        float4 c = un[i];
        br += hh.x * a.x + hh.y * a.y + hh.z * a.z + hh.w * a.w;
        bz += hh.x * b.x + hh.y * b.y + hh.z * b.z + hh.w * b.w;
        bn += hh.x * c.x + hh.y * c.y + hh.z * c.z + hh.w * c.w;
    }

    ar = warp_sum(ar); az = warp_sum(az); an = warp_sum(an);
    br = warp_sum(br); bz = warp_sum(bz); bn = warp_sum(bn);

    if (lane == 0) {
        float ir = ar + b_ih[warp];
        float iz = az + b_ih[warp + H];
        float in_ = an + b_ih[warp + 2 * H];
        float hr = br + b_hh[warp];
        float hz = bz + b_hh[warp + H];
        float hn = bn + b_hh[warp + 2 * H];
        float r = 1.f / (1.f + expf(-(ir + hr)));
        float z = 1.f / (1.f + expf(-(iz + hz)));
        float n = tanhf(in_ + r * hn);
        float hp = h_prev[warp];
        float ho = (1.f - z) * n + z * hp;
        g_h1[warp] = ho;
        out_hidden[warp] = ho;
    }
}

// ---------------- v partials: weighted row-sum of Wa (coalesced) ----------------
__global__ void k_v_part(const float* __restrict__ Wa) {
    __shared__ float hsh[16];
    int tid = threadIdx.x;  // 128
    int r0 = blockIdx.y * 16;
    if (tid < 16) hsh[tid] = g_h1[r0 + tid];
    __syncthreads();
    int j = blockIdx.x * 128 + tid;
    float a0 = 0.f, a1 = 0.f, a2 = 0.f, a3 = 0.f;
    #pragma unroll
    for (int ss = 0; ss < 16; ss += 4) {
        a0 += hsh[ss + 0] * Wa[(size_t)(r0 + ss + 0) * H + j];
        a1 += hsh[ss + 1] * Wa[(size_t)(r0 + ss + 1) * H + j];
        a2 += hsh[ss + 2] * Wa[(size_t)(r0 + ss + 2) * H + j];
        a3 += hsh[ss + 3] * Wa[(size_t)(r0 + ss + 3) * H + j];
    }
    g_vpart[blockIdx.y * H + j] = (a0 + a1) + (a2 + a3);
}

// ---------------- v = reduce(vpart) ; c = ba.h1 ----------------
__global__ void k_v_reduce(const float* __restrict__ ba) {
    int tid = threadIdx.x;  // 256
    if (blockIdx.x == 4) {
        float a = 0.f;
        for (int i = tid; i < H; i += 256) a += ba[i] * g_h1[i];
        a = warp_sum(a);
        __shared__ float red[8];
        if ((tid & 31) == 0) red[tid >> 5] = a;
        __syncthreads();
        if (tid == 0) {
            float s = 0.f;
            #pragma unroll
            for (int i = 0; i < 8; i++) s += red[i];
            g_c = s;
        }
        return;
    }
    int j = blockIdx.x * 256 + tid;
    float a = 0.f;
    #pragma unroll
    for (int y = 0; y < 64; y++) a += g_vpart[y * H + j];
    g_v[j] = a;
}

// ---------------- scores[s] = enc[s,:].v + c  (warp per s) ----------------
__global__ void k_scores(const float* __restrict__ enc) {
    int warp = (blockIdx.x * blockDim.x + threadIdx.x) >> 5;
    int lane = threadIdx.x & 31;
    if (warp >= SEQ) return;
    const float4* e = (const float4*)(enc + (size_t)warp * H);
    const float4* vv = (const float4*)g_v;
    float acc = 0.f;
    #pragma unroll
    for (int t = 0; t < H / 128; t++) {
        int i = lane + t * 32;
        float4 a = e[i];
        float4 b = vv[i];
        acc += a.x * b.x + a.y * b.y + a.z * b.z + a.w * b.w;
    }
    acc = warp_sum(acc);
    if (lane == 0) g_scores[warp] = acc + g_c;
}

// ---------------- softmax over 2048 scores (single block) ----------------
__global__ void k_softmax(float* __restrict__ out_attn) {
    __shared__ float red[32];
    __shared__ float bc;
    int tid = threadIdx.x;  // 1024

    float m = -1e30f;
    for (int s = tid; s < SEQ; s += 1024) m = fmaxf(m, g_scores[s]);
    m = warp_max(m);
    if ((tid & 31) == 0) red[tid >> 5] = m;
    __syncthreads();
    if (tid < 32) {
        float v = warp_max(red[tid]);
        if (tid == 0) bc = v;
    }
    __syncthreads();
    float M = bc;

    float sum = 0.f;
    for (int s = tid; s < SEQ; s += 1024) {
        float e = expf(g_scores[s] - M);
        g_attn[s] = e;
        sum += e;
    }
    sum = warp_sum(sum);
    if ((tid & 31) == 0) red[tid >> 5] = sum;
    __syncthreads();
    if (tid < 32) {
        float v = warp_sum(red[tid]);
        if (tid == 0) bc = 1.f / v;
    }
    __syncthreads();
    float inv = bc;
    for (int s = tid; s < SEQ; s += 1024) {
        float w = g_attn[s] * inv;
        g_attn[s] = w;
        out_attn[s] = w;
    }
}

// ---------------- context partials: 64 chunks of 32 rows (coalesced) ----------------
__global__ void k_ctx_part(const float* __restrict__ enc) {
    __shared__ float wsh[32];
    int tid = threadIdx.x;  // 128
    int s0 = blockIdx.y * 32;
    if (tid < 32) wsh[tid] = g_attn[s0 + tid];
    __syncthreads();
    int j = blockIdx.x * 128 + tid;
    float a0 = 0.f, a1 = 0.f, a2 = 0.f, a3 = 0.f;
    #pragma unroll
    for (int ss = 0; ss < 32; ss += 4) {
        a0 += wsh[ss + 0] * enc[(size_t)(s0 + ss + 0) * H + j];
        a1 += wsh[ss + 1] * enc[(size_t)(s0 + ss + 1) * H + j];
        a2 += wsh[ss + 2] * enc[(size_t)(s0 + ss + 2) * H + j];
        a3 += wsh[ss + 3] * enc[(size_t)(s0 + ss + 3) * H + j];
    }
    g_cpart[blockIdx.y * H + j] = (a0 + a1) + (a2 + a3);
}

// ---------------- reduce 64 partials -> context ----------------
__global__ void k_ctx_reduce(float* __restrict__ out_context) {
    int j = blockIdx.x * blockDim.x + threadIdx.x;
    if (j >= H) return;
    float a = 0.f;
    #pragma unroll
    for (int y = 0; y < 64; y++) a += g_cpart[y * H + j];
    g_context[j] = a;
    out_context[j] = a;
}

// ---------------- logits pass 1: W_out[:, :H] @ h1 + b_out ----------------
__global__ void k_logits_h1(const float* __restrict__ W_out, const float* __restrict__ b_out) {
    __shared__ __align__(16) float u[H];
    for (int k = threadIdx.x; k < H; k += 256) u[k] = g_h1[k];
    __syncthreads();

    int r = blockIdx.x * 8 + (threadIdx.x >> 5);
    if (r >= VOC) return;
    int lane = threadIdx.x & 31;
    const float4* w = (const float4*)(W_out + (size_t)r * (2 * H));
    const float4* uv = (const float4*)u;
    float acc0 = 0.f, acc1 = 0.f;
    #pragma unroll
    for (int t = 0; t < 4; t++) {
        int i0 = lane + (2 * t) * 32;
        int i1 = lane + (2 * t + 1) * 32;
        float4 a = w[i0];
        float4 b = uv[i0];
        acc0 += a.x * b.x + a.y * b.y + a.z * b.z + a.w * b.w;
        float4 c = w[i1];
        float4 d = uv[i1];
        acc1 += c.x * d.x + c.y * d.y + c.z * d.z + c.w * d.w;
    }
    float acc = warp_sum(acc0 + acc1);
    if (lane == 0) g_logits[r] = acc + b_out[r];
}

// ---------------- logits pass 2: += W_out[:, H:] @ context ----------------
__global__ void k_logits_ctx(const float* __restrict__ W_out) {
    __shared__ __align__(16) float u[H];
    for (int k = threadIdx.x; k < H; k += 256) u[k] = g_context[k];
    __syncthreads();

    int r = blockIdx.x * 8 + (threadIdx.x >> 5);
    if (r >= VOC) return;
    int lane = threadIdx.x & 31;
    const float4* w = (const float4*)(W_out + (size_t)r * (2 * H) + H);
    const float4* uv = (const float4*)u;
    float acc0 = 0.f, acc1 = 0.f;
    #pragma unroll
    for (int t = 0; t < 4; t++) {
        int i0 = lane + (2 * t) * 32;
        int i1 = lane + (2 * t + 1) * 32;
        float4 a = w[i0];
        float4 b = uv[i0];
        acc0 += a.x * b.x + a.y * b.y + a.z * b.z + a.w * b.w;
        float4 c = w[i1];
        float4 d = uv[i1];
        acc1 += c.x * d.x + c.y * d.y + c.z * d.z + c.w * d.w;
    }
    float acc = warp_sum(acc0 + acc1);
    if (lane == 0) g_logits[r] += acc;
}

// ---------------- lse pass 1: per-block (max, sum exp) ----------------
__global__ void k_lse1() {
    __shared__ float red[32];
    __shared__ float bc;
    int tid = threadIdx.x;  // 256
    const int chunk = (VOC + LSE_BLOCKS - 1) / LSE_BLOCKS;  // 786
    int lo = blockIdx.x * chunk;
    int hi = min(lo + chunk, VOC);

    float m = -1e30f;
    for (int r = lo + tid; r < hi; r += 256) m = fmaxf(m, g_logits[r]);
    m = warp_max(m);
    if ((tid & 31) == 0) red[tid >> 5] = m;
    __syncthreads();
    if (tid < 32) {
        float v = (tid < 8) ? red[tid] : -1e30f;
        v = warp_max(v);
        if (tid == 0) bc = v;
    }
    __syncthreads();
    float M = bc;

    float sum = 0.f;
    for (int r = lo + tid; r < hi; r += 256) sum += expf(g_logits[r] - M);
    sum = warp_sum(sum);
    if ((tid & 31) == 0) red[tid >> 5] = sum;
    __syncthreads();
    if (tid < 32) {
        float v = (tid < 8) ? red[tid] : 0.f;
        v = warp_sum(v);
        if (tid == 0) {
            g_lse_m[blockIdx.x] = M;
            g_lse_s[blockIdx.x] = v;
        }
    }
}

// ---------------- lse pass 2: combine partials -> logZ ----------------
__global__ void k_lse2() {
    float M = -1e30f;
    #pragma unroll
    for (int i = 0; i < LSE_BLOCKS; i++) M = fmaxf(M, g_lse_m[i]);
    float Z = 0.f;
    #pragma unroll
    for (int i = 0; i < LSE_BLOCKS; i++) Z += g_lse_s[i] * expf(g_lse_m[i] - M);
    g_logZ = M + logf(Z);
}

// ---------------- output = logits - logZ ----------------
__global__ void k_out(float* __restrict__ out) {
    float lz = g_logZ;
    for (int r = blockIdx.x * blockDim.x + threadIdx.x; r < VOC; r += gridDim.x * blockDim.x) {
        out[r] = g_logits[r] - lz;
    }
}

// ---------------- stream/event setup (static ctor: pre-baseline, pre-capture) ----------------
static cudaStream_t g_s1;
static cudaEvent_t g_e1, g_e2;

namespace {
struct StreamInit {
    StreamInit() {
        cudaStreamCreateWithFlags(&g_s1, cudaStreamNonBlocking);
        cudaEventCreateWithFlags(&g_e1, cudaEventDisableTiming);
        cudaEventCreateWithFlags(&g_e2, cudaEventDisableTiming);
        // Warm both streams so no lazy allocation happens inside kernel_launch.
        k_warm<<<1, 32>>>();
        k_warm<<<1, 32, 0, g_s1>>>();
        cudaEventRecord(g_e1, 0);
        cudaEventRecord(g_e2, g_s1);
        cudaDeviceSynchronize();
    }
};
StreamInit g_stream_init;
}

// ---------------- launch ----------------
extern "C" void kernel_launch(void* const* d_in, const int* in_sizes, int n_in,
                              void* d_out, int out_size) {
    const int*   word         = (const int*)  d_in[0];
    const float* last_context = (const float*)d_in[1];
    const float* last_hidden  = (const float*)d_in[2];
    const float* enc          = (const float*)d_in[3];
    const float* emb          = (const float*)d_in[4];
    const float* W_ih0        = (const float*)d_in[5];
    const float* W_hh0        = (const float*)d_in[6];
    const float* b_ih0        = (const float*)d_in[7];
    const float* b_hh0        = (const float*)d_in[8];
    const float* W_ih1        = (const float*)d_in[9];
    const float* W_hh1        = (const float*)d_in[10];
    const float* b_ih1        = (const float*)d_in[11];
    const float* b_hh1        = (const float*)d_in[12];
    const float* Wa           = (const float*)d_in[13];
    const float* ba           = (const float*)d_in[14];
    const float* W_out        = (const float*)d_in[15];
    const float* b_out        = (const float*)d_in[16];
    float* out = (float*)d_out;

    // d_out layout: [output VOC | context H | hidden 2H | attn SEQ]
    float* out_context = out + VOC;
    float* out_h0      = out + VOC + H;
    float* out_h1      = out + VOC + 2 * H;
    float* out_attn    = out + VOC + 3 * H;

    // Serial GRU chain on main stream
    k_gru0<<<128, 256>>>(word, emb, last_context, W_ih0, W_hh0, b_ih0, b_hh0,
                         last_hidden, out_h0);
    k_gru1<<<128, 256>>>(W_ih1, W_hh1, b_ih1, b_hh1, last_hidden + H, out_h1);

    // Fork: attention chain on side stream, hidden under logits_h1 on main stream
    cudaEventRecord(g_e1, 0);
    cudaStreamWaitEvent(g_s1, g_e1, 0);

    {
        dim3 g(8, 64);
        k_v_part<<<g, 128, 0, g_s1>>>(Wa);
    }
    k_v_reduce<<<5, 256, 0, g_s1>>>(ba);
    k_scores<<<SEQ / 8, 256, 0, g_s1>>>(enc);
    k_softmax<<<1, 1024, 0, g_s1>>>(out_attn);
    {
        dim3 g(8, 64);
        k_ctx_part<<<g, 128, 0, g_s1>>>(enc);
    }
    k_ctx_reduce<<<4, 256, 0, g_s1>>>(out_context);
    cudaEventRecord(g_e2, g_s1);

    // Concurrent with the above: first half of the big GEMV
    k_logits_h1<<<(VOC + 7) / 8, 256>>>(W_out, b_out);

    // Join, then second half + log-softmax
    cudaStreamWaitEvent(0, g_e2, 0);
    k_logits_ctx<<<(VOC + 7) / 8, 256>>>(W_out);
    k_lse1<<<LSE_BLOCKS, 256>>>();
    k_lse2<<<1, 1>>>();
    k_out<<<200, 256>>>(out);
}

// round 4
// speedup vs baseline: 1.6346x; 1.1192x over previous
#include <cuda_runtime.h>

#define H 1024
#define SEQ 2048
#define VOC 50257
#define LSE_BLOCKS 32

// ---------------- device scratch (static, allocation-guard safe) ----------------
__device__ __align__(16) float g_gi0[3 * H];
__device__ __align__(16) float g_gh0[3 * H];
__device__ __align__(16) float g_gi1[3 * H];
__device__ __align__(16) float g_gh1[3 * H];
__device__ __align__(16) float g_h0[H];
__device__ __align__(16) float g_h1[H];
__device__ __align__(16) float g_v[H];
__device__ float g_c;
__device__ __align__(16) float g_scores[SEQ];
__device__ __align__(16) float g_attn[SEQ];
__device__ __align__(16) float g_vpart[64 * H];
__device__ __align__(16) float g_cpart[64 * H];
__device__ __align__(16) float g_context[H];
__device__ __align__(16) float g_logits[VOC];
__device__ __align__(16) float g_logits2[VOC];
__device__ float g_lse_m[LSE_BLOCKS];
__device__ float g_lse_s[LSE_BLOCKS];

__device__ __forceinline__ float warp_sum(float v) {
    #pragma unroll
    for (int o = 16; o; o >>= 1) v += __shfl_xor_sync(0xffffffffu, v, o);
    return v;
}
__device__ __forceinline__ float warp_max(float v) {
    #pragma unroll
    for (int o = 16; o; o >>= 1) v = fmaxf(v, __shfl_xor_sync(0xffffffffu, v, o));
    return v;
}

__global__ void k_warm() {}

// ---------------- GRU0 GEMV: 6144 warps, one gate-row each ----------------
// warps [0,3072): g_gi0[w] = W_ih0[w,:] . [emb[word], last_context]
// warps [3072,6144): g_gh0[w-3072] = W_hh0[w-3072,:] . last_hidden[0]
__global__ void k_gru0_mv(const int* __restrict__ word,
                          const float* __restrict__ emb,
                          const float* __restrict__ last_context,
                          const float* __restrict__ W_ih,
                          const float* __restrict__ W_hh,
                          const float* __restrict__ h_prev) {
    int w = (blockIdx.x * blockDim.x + threadIdx.x) >> 5;
    int lane = threadIdx.x & 31;

    if (w < 3 * H) {
        int w0 = word[0];
        const float4* emb4 = (const float4*)(emb + (size_t)w0 * H);
        const float4* ctx4 = (const float4*)last_context;
        const float4* row = (const float4*)(W_ih + (size_t)w * (2 * H));
        float acc = 0.f;
        #pragma unroll
        for (int t = 0; t < 8; t++) {
            int i = lane + t * 32;
            float4 a = row[i];
            float4 x = emb4[i];
            acc += x.x * a.x + x.y * a.y + x.z * a.z + x.w * a.w;
        }
        #pragma unroll
        for (int t = 8; t < 16; t++) {
            int i = lane + t * 32;
            float4 a = row[i];
            float4 x = ctx4[i - 256];
            acc += x.x * a.x + x.y * a.y + x.z * a.z + x.w * a.w;
        }
        acc = warp_sum(acc);
        if (lane == 0) g_gi0[w] = acc;
    } else {
        int r = w - 3 * H;
        const float4* row = (const float4*)(W_hh + (size_t)r * H);
        const float4* hv = (const float4*)h_prev;
        float acc = 0.f;
        #pragma unroll
        for (int t = 0; t < 8; t++) {
            int i = lane + t * 32;
            float4 a = row[i];
            float4 x = hv[i];
            acc += x.x * a.x + x.y * a.y + x.z * a.z + x.w * a.w;
        }
        acc = warp_sum(acc);
        if (lane == 0) g_gh0[r] = acc;
    }
}

// ---------------- GRU1 GEMV: 6144 warps, all len-1024 dots ----------------
__global__ void k_gru1_mv(const float* __restrict__ W_ih,
                          const float* __restrict__ W_hh,
                          const float* __restrict__ h_prev) {
    int w = (blockIdx.x * blockDim.x + threadIdx.x) >> 5;
    int lane = threadIdx.x & 31;

    const float4* row;
    const float4* xv;
    if (w < 3 * H) {
        row = (const float4*)(W_ih + (size_t)w * H);
        xv = (const float4*)g_h0;
    } else {
        row = (const float4*)(W_hh + (size_t)(w - 3 * H) * H);
        xv = (const float4*)h_prev;
    }
    float acc = 0.f;
    #pragma unroll
    for (int t = 0; t < 8; t++) {
        int i = lane + t * 32;
        float4 a = row[i];
        float4 x = xv[i];
        acc += x.x * a.x + x.y * a.y + x.z * a.z + x.w * a.w;
    }
    acc = warp_sum(acc);
    if (lane == 0) {
        if (w < 3 * H) g_gi1[w] = acc;
        else g_gh1[w - 3 * H] = acc;
    }
}

// ---------------- GRU combine: apply gates ----------------
template <bool FIRST>
__global__ void k_gru_comb(const float* __restrict__ b_ih, const float* __restrict__ b_hh,
                           const float* __restrict__ h_prev, float* __restrict__ out_hidden) {
    int j = blockIdx.x * blockDim.x + threadIdx.x;
    if (j >= H) return;
    const float* gi = FIRST ? g_gi0 : g_gi1;
    const float* gh = FIRST ? g_gh0 : g_gh1;
    float ir = gi[j]         + b_ih[j];
    float iz = gi[j + H]     + b_ih[j + H];
    float in_ = gi[j + 2 * H] + b_ih[j + 2 * H];
    float hr = gh[j]         + b_hh[j];
    float hz = gh[j + H]     + b_hh[j + H];
    float hn = gh[j + 2 * H] + b_hh[j + 2 * H];
    float r = 1.f / (1.f + expf(-(ir + hr)));
    float z = 1.f / (1.f + expf(-(iz + hz)));
    float n = tanhf(in_ + r * hn);
    float hp = h_prev[j];
    float ho = (1.f - z) * n + z * hp;
    if (FIRST) g_h0[j] = ho; else g_h1[j] = ho;
    out_hidden[j] = ho;
}

// ---------------- v partials: weighted row-sum of Wa (coalesced) ----------------
__global__ void k_v_part(const float* __restrict__ Wa) {
    __shared__ float hsh[16];
    int tid = threadIdx.x;  // 128
    int r0 = blockIdx.y * 16;
    if (tid < 16) hsh[tid] = g_h1[r0 + tid];
    __syncthreads();
    int j = blockIdx.x * 128 + tid;
    float a0 = 0.f, a1 = 0.f, a2 = 0.f, a3 = 0.f;
    #pragma unroll
    for (int ss = 0; ss < 16; ss += 4) {
        a0 += hsh[ss + 0] * Wa[(size_t)(r0 + ss + 0) * H + j];
        a1 += hsh[ss + 1] * Wa[(size_t)(r0 + ss + 1) * H + j];
        a2 += hsh[ss + 2] * Wa[(size_t)(r0 + ss + 2) * H + j];
        a3 += hsh[ss + 3] * Wa[(size_t)(r0 + ss + 3) * H + j];
    }
    g_vpart[blockIdx.y * H + j] = (a0 + a1) + (a2 + a3);
}

// ---------------- v = reduce(vpart) ; c = ba.h1 ----------------
__global__ void k_v_reduce(const float* __restrict__ ba) {
    int tid = threadIdx.x;  // 256
    if (blockIdx.x == 4) {
        float a = 0.f;
        for (int i = tid; i < H; i += 256) a += ba[i] * g_h1[i];
        a = warp_sum(a);
        __shared__ float red[8];
        if ((tid & 31) == 0) red[tid >> 5] = a;
        __syncthreads();
        if (tid == 0) {
            float s = 0.f;
            #pragma unroll
            for (int i = 0; i < 8; i++) s += red[i];
            g_c = s;
        }
        return;
    }
    int j = blockIdx.x * 256 + tid;
    float a = 0.f;
    #pragma unroll
    for (int y = 0; y < 64; y++) a += g_vpart[y * H + j];
    g_v[j] = a;
}

// ---------------- scores[s] = enc[s,:].v + c  (warp per s) ----------------
__global__ void k_scores(const float* __restrict__ enc) {
    int warp = (blockIdx.x * blockDim.x + threadIdx.x) >> 5;
    int lane = threadIdx.x & 31;
    if (warp >= SEQ) return;
    const float4* e = (const float4*)(enc + (size_t)warp * H);
    const float4* vv = (const float4*)g_v;
    float acc = 0.f;
    #pragma unroll
    for (int t = 0; t < H / 128; t++) {
        int i = lane + t * 32;
        float4 a = e[i];
        float4 b = vv[i];
        acc += a.x * b.x + a.y * b.y + a.z * b.z + a.w * b.w;
    }
    acc = warp_sum(acc);
    if (lane == 0) g_scores[warp] = acc + g_c;
}

// ---------------- softmax over 2048 scores (single block) ----------------
__global__ void k_softmax(float* __restrict__ out_attn) {
    __shared__ float red[32];
    __shared__ float bc;
    int tid = threadIdx.x;  // 1024

    float m = -1e30f;
    for (int s = tid; s < SEQ; s += 1024) m = fmaxf(m, g_scores[s]);
    m = warp_max(m);
    if ((tid & 31) == 0) red[tid >> 5] = m;
    __syncthreads();
    if (tid < 32) {
        float v = warp_max(red[tid]);
        if (tid == 0) bc = v;
    }
    __syncthreads();
    float M = bc;

    float sum = 0.f;
    for (int s = tid; s < SEQ; s += 1024) {
        float e = expf(g_scores[s] - M);
        g_attn[s] = e;
        sum += e;
    }
    sum = warp_sum(sum);
    if ((tid & 31) == 0) red[tid >> 5] = sum;
    __syncthreads();
    if (tid < 32) {
        float v = warp_sum(red[tid]);
        if (tid == 0) bc = 1.f / v;
    }
    __syncthreads();
    float inv = bc;
    for (int s = tid; s < SEQ; s += 1024) {
        float w = g_attn[s] * inv;
        g_attn[s] = w;
        out_attn[s] = w;
    }
}

// ---------------- context partials: 64 chunks of 32 rows (coalesced) ----------------
__global__ void k_ctx_part(const float* __restrict__ enc) {
    __shared__ float wsh[32];
    int tid = threadIdx.x;  // 128
    int s0 = blockIdx.y * 32;
    if (tid < 32) wsh[tid] = g_attn[s0 + tid];
    __syncthreads();
    int j = blockIdx.x * 128 + tid;
    float a0 = 0.f, a1 = 0.f, a2 = 0.f, a3 = 0.f;
    #pragma unroll
    for (int ss = 0; ss < 32; ss += 4) {
        a0 += wsh[ss + 0] * enc[(size_t)(s0 + ss + 0) * H + j];
        a1 += wsh[ss + 1] * enc[(size_t)(s0 + ss + 1) * H + j];
        a2 += wsh[ss + 2] * enc[(size_t)(s0 + ss + 2) * H + j];
        a3 += wsh[ss + 3] * enc[(size_t)(s0 + ss + 3) * H + j];
    }
    g_cpart[blockIdx.y * H + j] = (a0 + a1) + (a2 + a3);
}

// ---------------- reduce 64 partials -> context ----------------
__global__ void k_ctx_reduce(float* __restrict__ out_context) {
    int j = blockIdx.x * blockDim.x + threadIdx.x;
    if (j >= H) return;
    float a = 0.f;
    #pragma unroll
    for (int y = 0; y < 64; y++) a += g_cpart[y * H + j];
    g_context[j] = a;
    out_context[j] = a;
}

// ---------------- logits pass A: W_out[:, :H] @ h1 + b_out -> g_logits ----------------
__global__ void k_logits_h1(const float* __restrict__ W_out, const float* __restrict__ b_out) {
    __shared__ __align__(16) float u[H];
    for (int k = threadIdx.x; k < H; k += 256) u[k] = g_h1[k];
    __syncthreads();

    int r = blockIdx.x * 8 + (threadIdx.x >> 5);
    if (r >= VOC) return;
    int lane = threadIdx.x & 31;
    const float4* w = (const float4*)(W_out + (size_t)r * (2 * H));
    const float4* uv = (const float4*)u;
    float acc0 = 0.f, acc1 = 0.f;
    #pragma unroll
    for (int t = 0; t < 4; t++) {
        int i0 = lane + (2 * t) * 32;
        int i1 = lane + (2 * t + 1) * 32;
        float4 a = w[i0];
        float4 b = uv[i0];
        acc0 += a.x * b.x + a.y * b.y + a.z * b.z + a.w * b.w;
        float4 c = w[i1];
        float4 d = uv[i1];
        acc1 += c.x * d.x + c.y * d.y + c.z * d.z + c.w * d.w;
    }
    float acc = warp_sum(acc0 + acc1);
    if (lane == 0) g_logits[r] = acc + b_out[r];
}

// ---------------- logits pass B: W_out[:, H:] @ context -> g_logits2 (independent) ----------------
__global__ void k_logits_ctx(const float* __restrict__ W_out) {
    __shared__ __align__(16) float u[H];
    for (int k = threadIdx.x; k < H; k += 256) u[k] = g_context[k];
    __syncthreads();

    int r = blockIdx.x * 8 + (threadIdx.x >> 5);
    if (r >= VOC) return;
    int lane = threadIdx.x & 31;
    const float4* w = (const float4*)(W_out + (size_t)r * (2 * H) + H);
    const float4* uv = (const float4*)u;
    float acc0 = 0.f, acc1 = 0.f;
    #pragma unroll
    for (int t = 0; t < 4; t++) {
        int i0 = lane + (2 * t) * 32;
        int i1 = lane + (2 * t + 1) * 32;
        float4 a = w[i0];
        float4 b = uv[i0];
        acc0 += a.x * b.x + a.y * b.y + a.z * b.z + a.w * b.w;
        float4 c = w[i1];
        float4 d = uv[i1];
        acc1 += c.x * d.x + c.y * d.y + c.z * d.z + c.w * d.w;
    }
    float acc = warp_sum(acc0 + acc1);
    if (lane == 0) g_logits2[r] = acc;
}

// ---------------- lse pass 1: per-block (max, sum exp) over logits+logits2 ----------------
__global__ void k_lse1() {
    __shared__ float red[8];
    __shared__ float bc;
    int tid = threadIdx.x;  // 256
    const int chunk = (VOC + LSE_BLOCKS - 1) / LSE_BLOCKS;
    int lo = blockIdx.x * chunk;
    int hi = min(lo + chunk, VOC);

    float m = -1e30f;
    for (int r = lo + tid; r < hi; r += 256) m = fmaxf(m, g_logits[r] + g_logits2[r]);
    m = warp_max(m);
    if ((tid & 31) == 0) red[tid >> 5] = m;
    __syncthreads();
    if (tid < 32) {
        float v = (tid < 8) ? red[tid] : -1e30f;
        v = warp_max(v);
        if (tid == 0) bc = v;
    }
    __syncthreads();
    float M = bc;

    float sum = 0.f;
    for (int r = lo + tid; r < hi; r += 256) sum += expf(g_logits[r] + g_logits2[r] - M);
    sum = warp_sum(sum);
    if ((tid & 31) == 0) red[tid >> 5] = sum;
    __syncthreads();
    if (tid < 32) {
        float v = (tid < 8) ? red[tid] : 0.f;
        v = warp_sum(v);
        if (tid == 0) {
            g_lse_m[blockIdx.x] = M;
            g_lse_s[blockIdx.x] = v;
        }
    }
}

// ---------------- output: combine partial lse (one warp) then subtract ----------------
__global__ void k_out(float* __restrict__ out) {
    __shared__ float sLogZ;
    int tid = threadIdx.x;
    if (tid < 32) {
        float m = g_lse_m[tid];
        float M = warp_max(m);
        float v = g_lse_s[tid] * expf(m - M);
        float Z = warp_sum(v);
        if (tid == 0) sLogZ = M + logf(Z);
    }
    __syncthreads();
    float lz = sLogZ;
    for (int r = blockIdx.x * blockDim.x + tid; r < VOC; r += gridDim.x * blockDim.x) {
        out[r] = g_logits[r] + g_logits2[r] - lz;
    }
}

// ---------------- stream/event setup (static ctor: pre-baseline, pre-capture) ----------------
static cudaStream_t g_s1;
static cudaEvent_t g_e1, g_e2;

namespace {
struct StreamInit {
    StreamInit() {
        cudaStreamCreateWithFlags(&g_s1, cudaStreamNonBlocking);
        cudaEventCreateWithFlags(&g_e1, cudaEventDisableTiming);
        cudaEventCreateWithFlags(&g_e2, cudaEventDisableTiming);
        k_warm<<<1, 32>>>();
        k_warm<<<1, 32, 0, g_s1>>>();
        cudaEventRecord(g_e1, 0);
        cudaEventRecord(g_e2, g_s1);
        cudaDeviceSynchronize();
    }
};
StreamInit g_stream_init;
}

// ---------------- launch ----------------
extern "C" void kernel_launch(void* const* d_in, const int* in_sizes, int n_in,
                              void* d_out, int out_size) {
    const int*   word         = (const int*)  d_in[0];
    const float* last_context = (const float*)d_in[1];
    const float* last_hidden  = (const float*)d_in[2];
    const float* enc          = (const float*)d_in[3];
    const float* emb          = (const float*)d_in[4];
    const float* W_ih0        = (const float*)d_in[5];
    const float* W_hh0        = (const float*)d_in[6];
    const float* b_ih0        = (const float*)d_in[7];
    const float* b_hh0        = (const float*)d_in[8];
    const float* W_ih1        = (const float*)d_in[9];
    const float* W_hh1        = (const float*)d_in[10];
    const float* b_ih1        = (const float*)d_in[11];
    const float* b_hh1        = (const float*)d_in[12];
    const float* Wa           = (const float*)d_in[13];
    const float* ba           = (const float*)d_in[14];
    const float* W_out        = (const float*)d_in[15];
    const float* b_out        = (const float*)d_in[16];
    float* out = (float*)d_out;

    // d_out layout: [output VOC | context H | hidden 2H | attn SEQ]
    float* out_context = out + VOC;
    float* out_h0      = out + VOC + H;
    float* out_h1      = out + VOC + 2 * H;
    float* out_attn    = out + VOC + 3 * H;

    // GRU chain (flat GEMV + combine), main stream
    k_gru0_mv<<<768, 256>>>(word, emb, last_context, W_ih0, W_hh0, last_hidden);
    k_gru_comb<true ><<<4, 256>>>(b_ih0, b_hh0, last_hidden,     out_h0);
    k_gru1_mv<<<768, 256>>>(W_ih1, W_hh1, last_hidden + H);
    k_gru_comb<false><<<4, 256>>>(b_ih1, b_hh1, last_hidden + H, out_h1);

    // Fork: attention chain + logits_ctx on side stream
    cudaEventRecord(g_e1, 0);
    cudaStreamWaitEvent(g_s1, g_e1, 0);

    {
        dim3 g(8, 64);
        k_v_part<<<g, 128, 0, g_s1>>>(Wa);
    }
    k_v_reduce<<<5, 256, 0, g_s1>>>(ba);
    k_scores<<<SEQ / 8, 256, 0, g_s1>>>(enc);
    k_softmax<<<1, 1024, 0, g_s1>>>(out_attn);
    {
        dim3 g(8, 64);
        k_ctx_part<<<g, 128, 0, g_s1>>>(enc);
    }
    k_ctx_reduce<<<4, 256, 0, g_s1>>>(out_context);
    k_logits_ctx<<<(VOC + 7) / 8, 256, 0, g_s1>>>(W_out);
    cudaEventRecord(g_e2, g_s1);

    // Concurrent: first half of the big GEMV on main stream
    k_logits_h1<<<(VOC + 7) / 8, 256>>>(W_out, b_out);

    // Join, then log-softmax
    cudaStreamWaitEvent(0, g_e2, 0);
    k_lse1<<<LSE_BLOCKS, 256>>>();
    k_out<<<200, 256>>>(out);
}